// round 8
// baseline (speedup 1.0000x reference)
#include <cuda_runtime.h>
#include <cuda_fp16.h>
#include <cstdint>

#define NB   32
#define NH   64
#define NW   64
#define HO   62
#define WO   62
#define NPB  (HO*WO)            // 3844

// packed fp16 x: word = (ch even lo, ch odd hi); layout [b][c2 32][h][w], +pad
__device__ __align__(16) uint32_t g_x16[NB*32*NH*NW + 16];   // 16.78 MB
// A: [g 12][kw 3][oc 128][slot 8] fp16x2
__device__ __align__(16) uint32_t g_a16[36*1024];            // 147.5 KB

// ---- SMEM geometry (words per buffer) ----
#define AWRD  3072              // 3 kw tiles x 128 oc x 8 slots
#define BWRD  1088              // 8 c2 x 2 rows x 68
#define STW   (AWRD + BWRD)     // 4160
#define NBUF  4
#define SMEMB (NBUF*STW*4)      // 66560 B

// ---------------- PTX helpers ----------------
__device__ __forceinline__ uint32_t cvta_s(const void* p) {
    uint32_t a;
    asm("{ .reg .u64 t; cvta.to.shared.u64 t, %1; cvt.u32.u64 %0, t; }" : "=r"(a) : "l"(p));
    return a;
}
__device__ __forceinline__ uint32_t pack_h2(float even, float odd) {
    uint32_t d;
    asm("cvt.rn.f16x2.f32 %0, %1, %2;" : "=r"(d) : "f"(odd), "f"(even));
    return d;
}
__device__ __forceinline__ uint2 lds64(uint32_t addr) {
    uint2 v;
    asm volatile("ld.shared.v2.b32 {%0,%1},[%2];" : "=r"(v.x), "=r"(v.y) : "r"(addr));
    return v;
}
__device__ __forceinline__ uint32_t lds32(uint32_t addr) {
    uint32_t v;
    asm volatile("ld.shared.b32 %0,[%1];" : "=r"(v) : "r"(addr));
    return v;
}
#define CP_A16(dst, src) asm volatile("cp.async.cg.shared.global [%0],[%1],16;" :: "r"(dst), "l"(src))
#define CP_COMMIT()      asm volatile("cp.async.commit_group;" ::: "memory")
#define CP_WAIT0()       asm volatile("cp.async.wait_group 0;" ::: "memory")
#define CP_WAIT1()       asm volatile("cp.async.wait_group 1;" ::: "memory")
#define CP_WAIT2()       asm volatile("cp.async.wait_group 2;" ::: "memory")

// fp16-accumulate HMMA: D(f16) = A*B + C(f16)
__device__ __forceinline__ void mma_h(uint32_t* c, const uint32_t* a, const uint32_t* b) {
    asm volatile(
        "mma.sync.aligned.m16n8k16.row.col.f16.f16.f16.f16 "
        "{%0,%1},{%2,%3,%4,%5},{%6,%7},{%0,%1};"
        : "+r"(c[0]), "+r"(c[1])
        : "r"(a[0]), "r"(a[1]), "r"(a[2]), "r"(a[3]), "r"(b[0]), "r"(b[1]));
}

// ---------------- prep kernels ----------------
__global__ void prep_x16(const float* __restrict__ x) {
    int t = blockIdx.x * 256 + threadIdx.x;      // 1,048,576
    int b    = t >> 15;
    int r    = t & 32767;
    int c2   = r >> 10;
    int pos4 = r & 1023;
    const float4* pe = (const float4*)(x + ((size_t)b * 64 + 2*c2)     * (NH*NW)) + pos4;
    const float4* po = (const float4*)(x + ((size_t)b * 64 + 2*c2 + 1) * (NH*NW)) + pos4;
    float4 e = *pe, o = *po;
    uint4 d;
    d.x = pack_h2(e.x, o.x);
    d.y = pack_h2(e.y, o.y);
    d.z = pack_h2(e.z, o.z);
    d.w = pack_h2(e.w, o.w);
    ((uint4*)g_x16)[((size_t)b * 32 + c2) * 1024 + pos4] = d;
}

__global__ void prep_w(const float* __restrict__ w) {
    int idx = blockIdx.x * 256 + threadIdx.x;    // 36864
    int slot = idx & 7;
    int oc   = (idx >> 3) & 127;
    int sA   = idx >> 10;          // 0..35 = g*3 + kw
    int g    = sA / 3;
    int kw   = sA - g * 3;
    int kh   = g >> 2;
    int cblk = g & 3;
    int off  = kh * 3 + kw;
    int p    = (slot >> 1) + 4 * (slot & 1);
    int ce   = cblk * 16 + 2 * p;
    g_a16[idx] = pack_h2(w[oc * 576 + ce * 9 + off], w[oc * 576 + (ce + 1) * 9 + off]);
}

// ---------------- main kernel ----------------
__global__ __launch_bounds__(256, 1) void conv_main(float* __restrict__ out) {
    extern __shared__ __align__(16) uint32_t sm[];

    const int tid  = threadIdx.x;
    const int lane = tid & 31;
    const int warp = tid >> 5;
    const int wm   = warp >> 2;        // 0..1 : oc half
    const int wn   = warp & 3;
    const int rW   = wn >> 1;          // output row within tile
    const int cW   = (wn & 1) * 32;    // wo base

    const int b   = blockIdx.y;
    const int ho0 = blockIdx.x * 2;

    const uint32_t smem_b = cvta_s(sm);
    const uint32_t* xb = g_x16 + (size_t)b * (32 * NH * NW);

    // ---- B staging descriptors: 272 x 16B ops ----
    uint32_t bd0, bs0, bd1 = 0, bs1 = 0;
    {
        int i = tid, run = i / 17, q = i - run * 17;
        int c2 = run >> 1, r = run & 1;
        bd0 = (uint32_t)(AWRD + c2 * 136 + r * 68 + q * 4);
        bs0 = (uint32_t)(c2 * 4096 + (ho0 + r) * 64 + q * 4);
        if (tid < 16) {
            int i2 = 256 + tid, run2 = i2 / 17, q2 = i2 - run2 * 17;
            int c22 = run2 >> 1, r2 = run2 & 1;
            bd1 = (uint32_t)(AWRD + c22 * 136 + r2 * 68 + q2 * 4);
            bs1 = (uint32_t)(c22 * 4096 + (ho0 + r2) * 64 + q2 * 4);
        }
    }

    float acc[4][4][4];
    #pragma unroll
    for (int mi = 0; mi < 4; ++mi)
        #pragma unroll
        for (int ni = 0; ni < 4; ++ni)
            #pragma unroll
            for (int q = 0; q < 4; ++q) acc[mi][ni][q] = 0.0f;

    const uint32_t a_fw = ((uint32_t)(wm * 64 + (lane >> 2)) * 8 + (lane & 3) * 2) * 4;
    const uint32_t b_fw = (uint32_t)(AWRD + (lane & 3) * 136 + rW * 68 + cW + (lane >> 2)) * 4;

    auto issue_stage = [&](int g, uint32_t bufw) {
        const int kh   = g >> 2;
        const int cblk = g & 3;
        const uint4* asrc = (const uint4*)(g_a16 + g * AWRD) + tid;
        const uint32_t adst = smem_b + bufw * 4 + (uint32_t)tid * 16;
        CP_A16(adst,        asrc);
        CP_A16(adst + 4096, asrc + 256);
        CP_A16(adst + 8192, asrc + 512);
        const uint32_t soff = (uint32_t)(cblk * 8 * 4096 + kh * 64);
        CP_A16(smem_b + (bufw + bd0) * 4, (const char*)(xb + bs0 + soff));
        if (tid < 16)
            CP_A16(smem_b + (bufw + bd1) * 4, (const char*)(xb + bs1 + soff));
        CP_COMMIT();
    };

    issue_stage(0, 0);
    issue_stage(1, STW);
    issue_stage(2, 2 * STW);

    uint32_t cbuf = 0;

    #pragma unroll 1
    for (int s = 0; s < 12; ++s) {
        if      (s < 10) { CP_WAIT2(); }
        else if (s == 10){ CP_WAIT1(); }
        else             { CP_WAIT0(); }
        __syncthreads();
        if (s + 3 < 12) issue_stage(s + 3, (cbuf + 3 * STW >= NBUF * STW)
                                           ? cbuf + 3 * STW - NBUF * STW
                                           : cbuf + 3 * STW);

        const uint32_t abase0 = smem_b + cbuf * 4 + a_fw;
        const uint32_t bbase0 = smem_b + cbuf * 4 + b_fw;

        // fp16 group accumulators for this stage (K=48)
        uint32_t acch[4][4][2];
        #pragma unroll
        for (int mi = 0; mi < 4; ++mi)
            #pragma unroll
            for (int ni = 0; ni < 4; ++ni) { acch[mi][ni][0] = 0u; acch[mi][ni][1] = 0u; }

        #pragma unroll
        for (int kw = 0; kw < 3; ++kw) {
            const uint32_t abase = abase0 + (uint32_t)kw * 4096;
            const uint32_t bbase = bbase0 + (uint32_t)kw * 4;

            uint32_t af[4][4], bf[4][2];
            #pragma unroll
            for (int mi = 0; mi < 4; ++mi) {
                uint2 t0 = lds64(abase + (uint32_t)mi * 512);
                uint2 t1 = lds64(abase + (uint32_t)(mi * 512 + 256));
                af[mi][0] = t0.x; af[mi][1] = t1.x; af[mi][2] = t0.y; af[mi][3] = t1.y;
            }
            #pragma unroll
            for (int ni = 0; ni < 4; ++ni) {
                bf[ni][0] = lds32(bbase + (uint32_t)ni * 32);
                bf[ni][1] = lds32(bbase + (uint32_t)ni * 32 + 2176);
            }
            #pragma unroll
            for (int mi = 0; mi < 4; ++mi)
                #pragma unroll
                for (int ni = 0; ni < 4; ++ni)
                    mma_h(acch[mi][ni], af[mi], bf[ni]);
        }

        // promote stage partials to fp32 masters
        #pragma unroll
        for (int mi = 0; mi < 4; ++mi)
            #pragma unroll
            for (int ni = 0; ni < 4; ++ni) {
                float2 lo = __half22float2(*reinterpret_cast<__half2*>(&acch[mi][ni][0]));
                float2 hi = __half22float2(*reinterpret_cast<__half2*>(&acch[mi][ni][1]));
                acc[mi][ni][0] += lo.x;
                acc[mi][ni][1] += lo.y;
                acc[mi][ni][2] += hi.x;
                acc[mi][ni][3] += hi.y;
            }

        cbuf += STW; if (cbuf == NBUF * STW) cbuf = 0;
    }

    // ---- epilogue ----
    const int orow = ho0 + rW;
    #pragma unroll
    for (int mi = 0; mi < 4; ++mi) {
        #pragma unroll
        for (int ni = 0; ni < 4; ++ni) {
            const int ocr = wm * 64 + mi * 16 + (lane >> 2);
            const int wo  = cW + ni * 8 + 2 * (lane & 3);
            if (wo < WO) {
                const size_t base = (size_t)orow * WO + wo;
                float* p0 = out + ((size_t)ocr * NB + b) * NPB + base;
                *(float2*)p0 = make_float2(acc[mi][ni][0], acc[mi][ni][1]);
                float* p1 = out + ((size_t)(ocr + 8) * NB + b) * NPB + base;
                *(float2*)p1 = make_float2(acc[mi][ni][2], acc[mi][ni][3]);
            }
        }
    }
}

// ---------------- launch ----------------
extern "C" void kernel_launch(void* const* d_in, const int* in_sizes, int n_in,
                              void* d_out, int out_size) {
    const float* x = (const float*)d_in[0];
    const float* w = (const float*)d_in[1];
    float* out = (float*)d_out;

    cudaFuncSetAttribute(conv_main, cudaFuncAttributeMaxDynamicSharedMemorySize, SMEMB);

    prep_x16<<<4096, 256>>>(x);
    prep_w<<<144, 256>>>(w);
    conv_main<<<dim3(31, NB), 256, SMEMB>>>(out);
}

// round 9
// speedup vs baseline: 1.3918x; 1.3918x over previous
#include <cuda_runtime.h>
#include <cstdint>

#define NB   32
#define NH   64
#define NW   64
#define HO   62
#define WO   62
#define NPB  (HO*WO)            // 3844

// A: [g 12][kw 3][oc 128][slot 8] fp16x2
__device__ __align__(16) uint32_t g_a16[36*1024];            // 147.5 KB

// ---- SMEM geometry (words per buffer) ----
#define AWRD  3072              // 3 kw tiles x 128 oc x 8 slots
#define BWRD  1088              // 8 c2 x 2 rows x 68
#define STW   (AWRD + BWRD)     // 4160
#define NBUF  3
#define SMEMB (NBUF*STW*4)      // 49920 B

// ---------------- PTX helpers ----------------
__device__ __forceinline__ uint32_t cvta_s(const void* p) {
    uint32_t a;
    asm("{ .reg .u64 t; cvta.to.shared.u64 t, %1; cvt.u32.u64 %0, t; }" : "=r"(a) : "l"(p));
    return a;
}
__device__ __forceinline__ uint32_t pack_h2(float even, float odd) {
    uint32_t d;
    asm("cvt.rn.f16x2.f32 %0, %1, %2;" : "=r"(d) : "f"(odd), "f"(even));  // lo=even, hi=odd
    return d;
}
__device__ __forceinline__ uint2 lds64(uint32_t addr) {
    uint2 v;
    asm volatile("ld.shared.v2.b32 {%0,%1},[%2];" : "=r"(v.x), "=r"(v.y) : "r"(addr));
    return v;
}
__device__ __forceinline__ uint32_t lds32(uint32_t addr) {
    uint32_t v;
    asm volatile("ld.shared.b32 %0,[%1];" : "=r"(v) : "r"(addr));
    return v;
}
__device__ __forceinline__ void sts128(uint32_t addr, uint4 v) {
    asm volatile("st.shared.v4.b32 [%0],{%1,%2,%3,%4};"
                 :: "r"(addr), "r"(v.x), "r"(v.y), "r"(v.z), "r"(v.w) : "memory");
}
#define CP_A16(dst, src) asm volatile("cp.async.cg.shared.global [%0],[%1],16;" :: "r"(dst), "l"(src))
#define CP_COMMIT()      asm volatile("cp.async.commit_group;" ::: "memory")
#define CP_WAIT0()       asm volatile("cp.async.wait_group 0;" ::: "memory")
#define CP_WAIT1()       asm volatile("cp.async.wait_group 1;" ::: "memory")

__device__ __forceinline__ void mma_f16(float* c, const uint32_t* a, const uint32_t* b) {
    asm volatile(
        "mma.sync.aligned.m16n8k16.row.col.f32.f16.f16.f32 "
        "{%0,%1,%2,%3},{%4,%5,%6,%7},{%8,%9},{%0,%1,%2,%3};"
        : "+f"(c[0]), "+f"(c[1]), "+f"(c[2]), "+f"(c[3])
        : "r"(a[0]), "r"(a[1]), "r"(a[2]), "r"(a[3]), "r"(b[0]), "r"(b[1]));
}

// ---------------- prep kernel (weights only) ----------------
__global__ void prep_w(const float* __restrict__ w) {
    int idx = blockIdx.x * 256 + threadIdx.x;    // 36864
    int slot = idx & 7;
    int oc   = (idx >> 3) & 127;
    int sA   = idx >> 10;          // 0..35 = g*3 + kw
    int g    = sA / 3;
    int kw   = sA - g * 3;
    int kh   = g >> 2;
    int cblk = g & 3;
    int off  = kh * 3 + kw;
    int p    = (slot >> 1) + 4 * (slot & 1);
    int ce   = cblk * 16 + 2 * p;
    g_a16[idx] = pack_h2(w[oc * 576 + ce * 9 + off], w[oc * 576 + (ce + 1) * 9 + off]);
}

// ---------------- main kernel ----------------
__global__ __launch_bounds__(256, 2) void conv_main(const float* __restrict__ x,
                                                    float* __restrict__ out) {
    extern __shared__ __align__(16) uint32_t sm[];

    const int tid  = threadIdx.x;
    const int lane = tid & 31;
    const int warp = tid >> 5;
    const int wm   = warp >> 2;        // 0..1 : oc half
    const int wn   = warp & 3;
    const int rW   = wn >> 1;          // output row within tile
    const int cW   = (wn & 1) * 32;    // wo base

    const int b   = blockIdx.y;
    const int ho0 = blockIdx.x * 2;

    const uint32_t smem_b = cvta_s(sm);

    // ---- B staging descriptors (fp32 source, fp16 pack) ----
    // group i (0..271): run=i/17, q=i%17 ; c2=run>>1, r=run&1
    // src cols 4*min(q,15) (q=16 dups cols 60..63 -> staged slots 64..67, only
    // ever consumed as discarded garbage operands)
    const float* bsrc0;
    uint32_t bdst0;
    {
        int run = tid / 17, q = tid - run * 17;
        int qe = (q > 15) ? 15 : q;
        int c2 = run >> 1, r = run & 1;
        bsrc0 = x + ((size_t)(b * 64 + 2 * c2)) * 4096 + (ho0 + r) * 64 + 4 * qe;
        bdst0 = (uint32_t)(AWRD + c2 * 136 + r * 68 + 4 * q);
    }
    const float* bsrc1 = x;
    uint32_t bdst1 = 0;
    const bool has1 = (tid < 16);
    if (has1) {
        int i2 = 256 + tid;
        int run2 = i2 / 17, q2 = i2 - run2 * 17;   // run2=15, q2=1..16
        int qe2 = (q2 > 15) ? 15 : q2;
        int c22 = run2 >> 1, r2 = run2 & 1;        // 7, 1
        bsrc1 = x + ((size_t)(b * 64 + 2 * c22)) * 4096 + (ho0 + r2) * 64 + 4 * qe2;
        bdst1 = (uint32_t)(AWRD + c22 * 136 + r2 * 68 + 4 * q2);
    }

    float acc[4][4][4];
    #pragma unroll
    for (int mi = 0; mi < 4; ++mi)
        #pragma unroll
        for (int ni = 0; ni < 4; ++ni)
            #pragma unroll
            for (int q = 0; q < 4; ++q) acc[mi][ni][q] = 0.0f;

    const uint32_t a_fw = ((uint32_t)(wm * 64 + (lane >> 2)) * 8 + (lane & 3) * 2) * 4;
    const uint32_t b_fw = (uint32_t)(AWRD + (lane & 3) * 136 + rW * 68 + cW + (lane >> 2)) * 4;

    auto issueA = [&](int g, uint32_t bufw) {
        const uint4* asrc = (const uint4*)(g_a16 + g * AWRD) + tid;
        const uint32_t adst = smem_b + bufw * 4 + (uint32_t)tid * 16;
        CP_A16(adst,        asrc);
        CP_A16(adst + 4096, asrc + 256);
        CP_A16(adst + 8192, asrc + 512);
        CP_COMMIT();
    };

    auto bSoff = [](int g) -> uint32_t {
        const int kh   = g >> 2;
        const int cblk = g & 3;
        return (uint32_t)(cblk * 16 * 4096 + kh * 64);    // floats
    };

    // ---- prologue ----
    issueA(0, 0);
    issueA(1, STW);
    {
        const uint32_t so = bSoff(0);
        float4 e0 = *(const float4*)(bsrc0 + so);
        float4 o0 = *(const float4*)(bsrc0 + so + 4096);
        uint4 v0;
        v0.x = pack_h2(e0.x, o0.x); v0.y = pack_h2(e0.y, o0.y);
        v0.z = pack_h2(e0.z, o0.z); v0.w = pack_h2(e0.w, o0.w);
        sts128(smem_b + bdst0 * 4, v0);
        if (has1) {
            float4 e1 = *(const float4*)(bsrc1 + so);
            float4 o1 = *(const float4*)(bsrc1 + so + 4096);
            uint4 v1;
            v1.x = pack_h2(e1.x, o1.x); v1.y = pack_h2(e1.y, o1.y);
            v1.z = pack_h2(e1.z, o1.z); v1.w = pack_h2(e1.w, o1.w);
            sts128(smem_b + bdst1 * 4, v1);
        }
    }

    uint32_t cbuf = 0;

    #pragma unroll 1
    for (int s = 0; s < 12; ++s) {
        if (s < 11) { CP_WAIT1(); } else { CP_WAIT0(); }
        __syncthreads();

        // prefetch A two ahead
        if (s + 2 < 12) {
            uint32_t b2 = cbuf + 2 * STW; if (b2 >= NBUF * STW) b2 -= NBUF * STW;
            issueA(s + 2, b2);
        }

        // issue B loads for next stage (consumed after compute)
        float4 e0, o0, e1, o1;
        const bool haveNext = (s + 1 < 12);
        if (haveNext) {
            const uint32_t so = bSoff(s + 1);
            e0 = *(const float4*)(bsrc0 + so);
            o0 = *(const float4*)(bsrc0 + so + 4096);
            if (has1) {
                e1 = *(const float4*)(bsrc1 + so);
                o1 = *(const float4*)(bsrc1 + so + 4096);
            }
        }

        // ---- compute stage s ----
        const uint32_t abase0 = smem_b + cbuf * 4 + a_fw;
        const uint32_t bbase0 = smem_b + cbuf * 4 + b_fw;

        #pragma unroll
        for (int kw = 0; kw < 3; ++kw) {
            const uint32_t abase = abase0 + (uint32_t)kw * 4096;
            const uint32_t bbase = bbase0 + (uint32_t)kw * 4;

            uint32_t af[4][4], bf[4][2];
            #pragma unroll
            for (int mi = 0; mi < 4; ++mi) {
                uint2 t0 = lds64(abase + (uint32_t)mi * 512);
                uint2 t1 = lds64(abase + (uint32_t)(mi * 512 + 256));
                af[mi][0] = t0.x; af[mi][1] = t1.x; af[mi][2] = t0.y; af[mi][3] = t1.y;
            }
            #pragma unroll
            for (int ni = 0; ni < 4; ++ni) {
                bf[ni][0] = lds32(bbase + (uint32_t)ni * 32);
                bf[ni][1] = lds32(bbase + (uint32_t)ni * 32 + 2176);
            }
            #pragma unroll
            for (int mi = 0; mi < 4; ++mi)
                #pragma unroll
                for (int ni = 0; ni < 4; ++ni)
                    mma_f16(acc[mi][ni], af[mi], bf[ni]);
        }

        // ---- pack + store B(s+1) into next buffer ----
        if (haveNext) {
            uint32_t nbuf = cbuf + STW; if (nbuf >= NBUF * STW) nbuf -= NBUF * STW;
            uint4 v0;
            v0.x = pack_h2(e0.x, o0.x); v0.y = pack_h2(e0.y, o0.y);
            v0.z = pack_h2(e0.z, o0.z); v0.w = pack_h2(e0.w, o0.w);
            sts128(smem_b + (nbuf + bdst0) * 4, v0);
            if (has1) {
                uint4 v1;
                v1.x = pack_h2(e1.x, o1.x); v1.y = pack_h2(e1.y, o1.y);
                v1.z = pack_h2(e1.z, o1.z); v1.w = pack_h2(e1.w, o1.w);
                sts128(smem_b + (nbuf + bdst1) * 4, v1);
            }
        }

        cbuf += STW; if (cbuf == NBUF * STW) cbuf = 0;
    }

    // ---- epilogue ----
    const int orow = ho0 + rW;
    #pragma unroll
    for (int mi = 0; mi < 4; ++mi) {
        #pragma unroll
        for (int ni = 0; ni < 4; ++ni) {
            const int ocr = wm * 64 + mi * 16 + (lane >> 2);
            const int wo  = cW + ni * 8 + 2 * (lane & 3);
            if (wo < WO) {
                const size_t base = (size_t)orow * WO + wo;
                float* p0 = out + ((size_t)ocr * NB + b) * NPB + base;
                *(float2*)p0 = make_float2(acc[mi][ni][0], acc[mi][ni][1]);
                float* p1 = out + ((size_t)(ocr + 8) * NB + b) * NPB + base;
                *(float2*)p1 = make_float2(acc[mi][ni][2], acc[mi][ni][3]);
            }
        }
    }
}

// ---------------- launch ----------------
extern "C" void kernel_launch(void* const* d_in, const int* in_sizes, int n_in,
                              void* d_out, int out_size) {
    const float* x = (const float*)d_in[0];
    const float* w = (const float*)d_in[1];
    float* out = (float*)d_out;

    cudaFuncSetAttribute(conv_main, cudaFuncAttributeMaxDynamicSharedMemorySize, SMEMB);

    prep_w<<<144, 256>>>(w);
    conv_main<<<dim3(31, NB), 256, SMEMB>>>(x, out);
}